// round 16
// baseline (speedup 1.0000x reference)
#include <cuda_runtime.h>
#include <cuda_fp16.h>
#include <cstdint>

// ---------------- fixed shapes ----------------
#define NS      51
#define T_LEN   2048
#define B_TOT   8192
#define M_ROWS  64
#define NCTA    (B_TOT / M_ROWS)      // 128
#define NTHREADS 384                  // 12 warps = 2 m-groups x 6 n-groups

// SMEM layout (bytes)
#define HPB     272                   // h tile pitch: 128 fp16 (hi|lo) + pad
#define HTSZ    (64 * HPB)            // 17408 per h tile
#define B1P     144                   // B1: [208 n][64 fp16]  (W1)
#define B2P     272                   // B2: [208 n][128 fp16] (Wi2|Wh2)

#define OFF_H1_0 0
#define OFF_H1_1 HTSZ
#define OFF_H2_0 (2 * HTSZ)
#define OFF_H2_1 (3 * HTSZ)
#define OFF_B1   (4 * HTSZ)               // 69632
#define OFF_B2   (OFF_B1 + 208 * B1P)     // 99584
#define OFF_B1Q  (OFF_B2 + 208 * B2P)     // 156160
#define OFF_B2Q  (OFF_B1Q + 832)
#define OFF_WXQ  (OFF_B2Q + 832)
#define OFF_WLS  (OFF_WXQ + 832)          // float[52] + pad
#define OFF_YW   (OFF_WLS + 224)          // float[2][64][8] parity-buffered
#define SMEM_TOTAL (OFF_YW + 2 * 64 * 8 * 4)   // 162976

typedef uint32_t u32;

// ---------------- helpers (fragment maps verified in R9) ----------------
__device__ __forceinline__ u32 smem_u32(const void* p) {
    u32 a;
    asm("{ .reg .u64 t; cvta.to.shared.u64 t, %1; cvt.u32.u64 %0, t; }" : "=r"(a) : "l"(p));
    return a;
}
__device__ __forceinline__ void ldsm4(u32* r, u32 addr) {
    asm volatile("ldmatrix.sync.aligned.m8n8.x4.shared.b16 {%0,%1,%2,%3}, [%4];"
                 : "=r"(r[0]), "=r"(r[1]), "=r"(r[2]), "=r"(r[3]) : "r"(addr));
}
__device__ __forceinline__ void mma_f16(float* c, const u32* a, const u32* b) {
    asm volatile("mma.sync.aligned.m16n8k16.row.col.f32.f16.f16.f32 "
                 "{%0,%1,%2,%3}, {%4,%5,%6,%7}, {%8,%9}, {%0,%1,%2,%3};"
                 : "+f"(c[0]), "+f"(c[1]), "+f"(c[2]), "+f"(c[3])
                 : "r"(a[0]), "r"(a[1]), "r"(a[2]), "r"(a[3]), "r"(b[0]), "r"(b[1]));
}
__device__ __forceinline__ float tanh_hw(float v) {
    float r; asm("tanh.approx.f32 %0, %1;" : "=f"(r) : "f"(v)); return r;
}
__device__ __forceinline__ float sigm(float v) {
    return fmaf(0.5f, tanh_hw(0.5f * v), 0.5f);
}

// A-fragment (m16k16) in an h tile; kchunk 0-3 = hi cols, 4-7 = lo cols
__device__ __forceinline__ u32 a_addr(u32 tile, int m0, int kchunk, int lane) {
    int r  = m0 + (lane & 15);
    int cb = kchunk * 32 + ((lane >> 4) << 4);
    return tile + r * HPB + cb;
}
// B-fragment x4 (one n8 tile, two k16 tiles starting at kchunk)
__device__ __forceinline__ u32 b_addr(u32 sbB, int pitch, int nt, int kchunk, int lane) {
    int n  = nt * 8 + (lane & 7);
    int cb = kchunk * 32 + ((lane >> 3) << 4);
    return sbB + n * pitch + cb;
}

// Regroup D-frag gates (verified): lane ends owning (i,f,g,o) of ONE (row,unit)
__device__ __forceinline__ void regroup(const float* C, int lane,
                                        float& gi_, float& gf, float& gg, float& go) {
    float v  = (lane & 1) ? C[0] : C[2];
    float sv = __shfl_xor_sync(0xFFFFFFFFu, v, 1);
    float w  = (lane & 1) ? C[1] : C[3];
    float sw = __shfl_xor_sync(0xFFFFFFFFu, w, 1);
    if (lane & 1) { gi_ = sv;   gf = sw;   gg = C[2]; go = C[3]; }
    else          { gi_ = C[0]; gf = C[1]; gg = sv;   go = sw;  }
}

// fp16 hi/lo split store of h into an h tile
__device__ __forceinline__ void store_h_tile(char* smem, int tileoff, int row, int j, float h) {
    __half hh = __float2half_rn(h);
    __half hl = __float2half_rn(h - __half2float(hh));
    *(__half*)(smem + tileoff + row * HPB + j * 2)       = hh;
    *(__half*)(smem + tileoff + row * HPB + 128 + j * 2) = hl;
}

// Layer-1 epilogue for ONE m-tile (no barrier: writes other h1 buffer)
__device__ __forceinline__ void epi_l1_mt(
    float acc[5][4], int cnt, int nt0, int lane, int jpar, int row,
    const float4* b1q, const float4* wxq, float xv,
    float* c1, char* smem, int h1off)
{
    #pragma unroll
    for (int nti = 0; nti < 5; ++nti) if (nti < cnt) {
        float gi_, gf, gg, go;
        regroup(acc[nti], lane, gi_, gf, gg, go);
        int j = 2 * (nt0 + nti) + jpar;
        float4 b  = b1q[j];
        float4 wx = wxq[j];
        float pi = fmaf(xv, wx.x, gi_ + b.x);
        float pf = fmaf(xv, wx.y, gf + b.y);
        float pg = fmaf(xv, wx.z, gg + b.z);
        float po = fmaf(xv, wx.w, go + b.w);
        float cn = fmaf(sigm(pf), c1[nti], sigm(pi) * tanh_hw(pg));
        c1[nti] = cn;
        float h = sigm(po) * tanh_hw(cn);
        if (j < NS) store_h_tile(smem, h1off, row, j, h);
    }
}

// Layer-2 epilogue (both m-tiles): writes h2 into OTHER buffer + y partials
__device__ __forceinline__ void epi_l2(
    float acc[2][5][4], int cnt, int nt0, int lane, int jpar, const int* rows,
    const float4* b2q, const float* wls,
    float c2[2][5], char* smem, int h2off, float* ywslot, int ng)
{
    #pragma unroll
    for (int mt = 0; mt < 2; ++mt) {
        float yp = 0.0f;
        #pragma unroll
        for (int nti = 0; nti < 5; ++nti) if (nti < cnt) {
            float gi_, gf, gg, go;
            regroup(acc[mt][nti], lane, gi_, gf, gg, go);
            int j = 2 * (nt0 + nti) + jpar;
            float4 b = b2q[j];
            float pi = gi_ + b.x, pf = gf + b.y, pg = gg + b.z, po = go + b.w;
            float cn = fmaf(sigm(pf), c2[mt][nti], sigm(pi) * tanh_hw(pg));
            c2[mt][nti] = cn;
            float h = sigm(po) * tanh_hw(cn);
            if (j < NS) {
                store_h_tile(smem, h2off, rows[mt], j, h);
                yp = fmaf(wls[j], h, yp);
            }
        }
        float ys = yp + __shfl_xor_sync(0xFFFFFFFFu, yp, 2);
        if (!(lane & 2)) ywslot[rows[mt] * 8 + ng] = ys;
    }
}

__global__ __launch_bounds__(NTHREADS, 1)
void lstm2_hmma16_kernel(
    const float* __restrict__ x,      // [B, T]
    const float* __restrict__ Wih1,   // [204, 1]
    const float* __restrict__ Whh1,   // [204, 51]
    const float* __restrict__ bih1,
    const float* __restrict__ bhh1,
    const float* __restrict__ Wih2,   // [204, 51]
    const float* __restrict__ Whh2,   // [204, 51]
    const float* __restrict__ bih2,
    const float* __restrict__ bhh2,
    const float* __restrict__ Wlin,   // [1, 51]
    const float* __restrict__ blin,
    float* __restrict__ out)          // [B, T]
{
    extern __shared__ char smem[];
    const u32 sb = smem_u32(smem);
    const int tid  = threadIdx.x;
    const int wid  = tid >> 5;
    const int lane = tid & 31;
    const int mg   = wid / 6;                 // m-group 0/1 (rows 0-31 / 32-63)
    const int ng   = wid % 6;                 // n-group
    const int cnt  = (ng < 2) ? 5 : 4;
    const int nt0  = (ng < 2) ? 5 * ng : 10 + 4 * (ng - 2);
    const int rb   = blockIdx.x * M_ROWS;
    const int gtid = tid - 192 * mg;          // tid within my m-group
    const int barid = mg + 1;

    for (int i = tid; i < SMEM_TOTAL / 4; i += NTHREADS) ((u32*)smem)[i] = 0;
    __syncthreads();

    float4* b1q = (float4*)(smem + OFF_B1Q);
    float4* b2q = (float4*)(smem + OFF_B2Q);
    float4* wxq = (float4*)(smem + OFF_WXQ);
    float*  wls = (float*)(smem + OFF_WLS);
    float*  yw  = (float*)(smem + OFF_YW);    // [2][64][8]

    // ---- stage weights: B row n = 4*j + gi, plain fp16 ----
    for (int idx = tid; idx < 208 * NS; idx += NTHREADS) {
        int n = idx / NS, m = idx % NS;
        int j = n >> 2, gi = n & 3;
        if (j < NS) {
            int g = gi * NS + j;
            *(__half*)(smem + OFF_B1 + n * B1P + m * 2)       = __float2half_rn(Whh1[g * NS + m]);
            *(__half*)(smem + OFF_B2 + n * B2P + m * 2)       = __float2half_rn(Wih2[g * NS + m]);
            *(__half*)(smem + OFF_B2 + n * B2P + 128 + m * 2) = __float2half_rn(Whh2[g * NS + m]);
        }
    }
    for (int j = tid; j < NS; j += NTHREADS) {
        b1q[j] = make_float4(bih1[j] + bhh1[j], bih1[j + NS] + bhh1[j + NS],
                             bih1[j + 2 * NS] + bhh1[j + 2 * NS], bih1[j + 3 * NS] + bhh1[j + 3 * NS]);
        b2q[j] = make_float4(bih2[j] + bhh2[j], bih2[j + NS] + bhh2[j + NS],
                             bih2[j + 2 * NS] + bhh2[j + 2 * NS], bih2[j + 3 * NS] + bhh2[j + 3 * NS]);
        wxq[j] = make_float4(Wih1[j], Wih1[j + NS], Wih1[j + 2 * NS], Wih1[j + 3 * NS]);
        wls[j] = Wlin[j];
    }
    __syncthreads();

    const float blin_v = blin[0];
    const int m0base = 32 * mg;
    const int rbase  = m0base + (lane >> 2) + 8 * (lane & 1);
    const int rows[2] = {rbase, rbase + 16};
    const int jpar = (lane >> 1) & 1;
    const u32 sbB1 = sb + OFF_B1;
    const u32 sbB2 = sb + OFF_B2;

    float c1[2][5], c2[2][5];
    #pragma unroll
    for (int mt = 0; mt < 2; ++mt)
        #pragma unroll
        for (int i = 0; i < 5; ++i) { c1[mt][i] = 0.0f; c2[mt][i] = 0.0f; }

    // ---- prologue: h1(0) = L1(x(0), h=0, c=0) into tile H1_0 ----
    {
        float acc0[5][4];
        #pragma unroll
        for (int i = 0; i < 5; ++i)
            #pragma unroll
            for (int q = 0; q < 4; ++q) acc0[i][q] = 0.0f;
        #pragma unroll
        for (int mt = 0; mt < 2; ++mt) {
            float xv0 = __ldg(&x[(size_t)(rb + rows[mt]) * T_LEN]);
            epi_l1_mt(acc0, cnt, nt0, lane, jpar, rows[mt], b1q, wxq, xv0,
                      c1[mt], smem, OFF_H1_0);
        }
    }
    __syncthreads();

    // ---- main loop: ONE group barrier per step ----
    for (int t = 0; t < T_LEN; ++t) {
        const int par = t & 1;
        const u32 h1cur   = sb + (par ? OFF_H1_1 : OFF_H1_0);
        const int h1nxtOf = par ? OFF_H1_0 : OFF_H1_1;
        const u32 h2cur   = sb + (par ? OFF_H2_1 : OFF_H2_0);
        const int h2nxtOf = par ? OFF_H2_0 : OFF_H2_1;

        // y(t-1) store (group-local rows) from parity slot (t-1)&1; overlapped
        if (gtid < 32 && t > 0) {
            int r = m0base + gtid;
            const float* ywp = yw + (par ^ 1) * 512;
            float acc = blin_v;
            #pragma unroll
            for (int g2 = 0; g2 < 6; ++g2) acc += ywp[r * 8 + g2];
            out[(size_t)(rb + r) * T_LEN + (t - 1)] = acc;
        }

        float xv[2];
        #pragma unroll
        for (int mt = 0; mt < 2; ++mt)
            xv[mt] = (t + 1 < T_LEN)
                   ? __ldg(&x[(size_t)(rb + rows[mt]) * T_LEN + t + 1]) : 0.0f;

        float acc2[2][5][4];
        #pragma unroll
        for (int mt = 0; mt < 2; ++mt)
            #pragma unroll
            for (int i = 0; i < 5; ++i)
                #pragma unroll
                for (int q = 0; q < 4; ++q) acc2[mt][i][q] = 0.0f;

        // ======= per m-tile: merged P1+P2 (shared h1 A-frags) -> epi_l1 -> P3 =======
        #pragma unroll
        for (int mt = 0; mt < 2; ++mt) {
            const int m0 = m0base + 16 * mt;
            float acc1[5][4];
            #pragma unroll
            for (int i = 0; i < 5; ++i)
                #pragma unroll
                for (int q = 0; q < 4; ++q) acc1[i][q] = 0.0f;

            // P12: load h1 A-frags once, feed both B1 (acc1) and B2-Wi2 (acc2[mt])
            #pragma unroll
            for (int half = 0; half < 2; ++half) {
                u32 ahi[2][4], alo[2][4];
                #pragma unroll
                for (int kk = 0; kk < 2; ++kk) {
                    ldsm4(ahi[kk], a_addr(h1cur, m0, 2 * half + kk, lane));
                    ldsm4(alo[kk], a_addr(h1cur, m0, 4 + 2 * half + kk, lane));
                }
                #pragma unroll
                for (int nti = 0; nti < 5; ++nti) if (nti < cnt) {
                    int nt = nt0 + nti;
                    u32 b1f[4], b2f[4];
                    ldsm4(b1f, b_addr(sbB1, B1P, nt, 2 * half, lane));
                    ldsm4(b2f, b_addr(sbB2, B2P, nt, 2 * half, lane));
                    #pragma unroll
                    for (int kk = 0; kk < 2; ++kk) {
                        mma_f16(acc1[nti], ahi[kk], b1f + 2 * kk);
                        mma_f16(acc1[nti], alo[kk], b1f + 2 * kk);
                    }
                    #pragma unroll
                    for (int kk = 0; kk < 2; ++kk) {
                        mma_f16(acc2[mt][nti], ahi[kk], b2f + 2 * kk);
                        mma_f16(acc2[mt][nti], alo[kk], b2f + 2 * kk);
                    }
                }
            }
            // epi_l1 for this m-tile (writes other h1 buffer; MUFU overlaps MMA stream)
            epi_l1_mt(acc1, cnt, nt0, lane, jpar, rows[mt], b1q, wxq, xv[mt],
                      c1[mt], smem, h1nxtOf);

            // P3: acc2[mt] += h2(t-1) * Wh2  (B2 kchunks 4-7)
            #pragma unroll
            for (int half = 0; half < 2; ++half) {
                u32 ahi[2][4], alo[2][4];
                #pragma unroll
                for (int kk = 0; kk < 2; ++kk) {
                    ldsm4(ahi[kk], a_addr(h2cur, m0, 2 * half + kk, lane));
                    ldsm4(alo[kk], a_addr(h2cur, m0, 4 + 2 * half + kk, lane));
                }
                #pragma unroll
                for (int nti = 0; nti < 5; ++nti) if (nti < cnt) {
                    int nt = nt0 + nti;
                    u32 b2f[4];
                    ldsm4(b2f, b_addr(sbB2, B2P, nt, 4 + 2 * half, lane));
                    #pragma unroll
                    for (int kk = 0; kk < 2; ++kk) {
                        mma_f16(acc2[mt][nti], ahi[kk], b2f + 2 * kk);
                        mma_f16(acc2[mt][nti], alo[kk], b2f + 2 * kk);
                    }
                }
            }
        }

        // epi_l2 writes the OTHER h2 buffer + yw parity slot t&1 (no WAR hazard)
        epi_l2(acc2, cnt, nt0, lane, jpar, rows, b2q, wls, c2, smem,
               h2nxtOf, yw + par * 512, ng);

        // single group barrier: all step-t writes visible before step t+1 reads
        asm volatile("bar.sync %0, 192;" :: "r"(barid) : "memory");
    }

    // ---- final projection: y(T-1) from parity slot (T-1)&1 ----
    if (gtid < 32) {
        int r = m0base + gtid;
        const float* ywp = yw + ((T_LEN - 1) & 1) * 512;
        float acc = blin_v;
        #pragma unroll
        for (int g2 = 0; g2 < 6; ++g2) acc += ywp[r * 8 + g2];
        out[(size_t)(rb + r) * T_LEN + (T_LEN - 1)] = acc;
    }
}

extern "C" void kernel_launch(void* const* d_in, const int* in_sizes, int n_in,
                              void* d_out, int out_size) {
    const float* x    = (const float*)d_in[0];
    const float* Wih1 = (const float*)d_in[1];
    const float* Whh1 = (const float*)d_in[2];
    const float* bih1 = (const float*)d_in[3];
    const float* bhh1 = (const float*)d_in[4];
    const float* Wih2 = (const float*)d_in[5];
    const float* Whh2 = (const float*)d_in[6];
    const float* bih2 = (const float*)d_in[7];
    const float* bhh2 = (const float*)d_in[8];
    const float* Wlin = (const float*)d_in[9];
    const float* blin = (const float*)d_in[10];
    float* out = (float*)d_out;

    cudaFuncSetAttribute(lstm2_hmma16_kernel,
                         cudaFuncAttributeMaxDynamicSharedMemorySize, SMEM_TOTAL);

    dim3 grid(NCTA);          // 128 CTAs x 64 rows
    dim3 block(NTHREADS);     // 384 threads = 12 warps
    lstm2_hmma16_kernel<<<grid, block, SMEM_TOTAL>>>(
        x, Wih1, Whh1, bih1, bhh1, Wih2, Whh2, bih2, bhh2, Wlin, blin, out);
}